// round 2
// baseline (speedup 1.0000x reference)
#include <cuda_runtime.h>
#include <cuda_bf16.h>

typedef unsigned long long ull;

#define B       8
#define DIM     2048
#define EMB     512
#define HID     512
#define VOC     32000
#define TLEN    32
#define OUT_BT  (TLEN * VOC)          /* 1024000: stride between batches in out */
#define NB_LOG  250                   /* blocks in logits kernel (250*128 = 32000) */
#define VB_LOG  128                   /* v rows per logits block */
#define NB_EP   148                   /* blocks in eproj kernel */
#define VCH_EP  217                   /* v rows per eproj block (148*217 >= 32000) */

/* ------------------------------------------------------------------ scratch */
__device__ __align__(16) float g_enc0 [B * DIM];
__device__ __align__(16) float g_enc1 [B * DIM];
__device__ __align__(16) float g_img  [B * EMB];
__device__ __align__(16) float g_h0   [B * HID];
__device__ __align__(16) float g_h1   [B * HID];
__device__ __align__(16) float g_e    [B * EMB];
__device__ __align__(16) float g_Ppart[NB_EP * B * EMB];
__device__ __align__(16) float g_Spart[NB_LOG * B];
__device__ __align__(16) float g_S    [TLEN * B];

/* ------------------------------------------------------------------ helpers */
__device__ __forceinline__ ull ffma2(ull a, ull b, ull c) {
    ull d;
    asm("fma.rn.f32x2 %0, %1, %2, %3;" : "=l"(d) : "l"(a), "l"(b), "l"(c));
    return d;
}
__device__ __forceinline__ ull pack2(float x, float y) {
    ull r;
    asm("mov.b64 %0, {%1, %2};" : "=l"(r) : "f"(x), "f"(y));
    return r;
}
__device__ __forceinline__ float2 unpack2(ull v) {
    float2 f;
    asm("mov.b64 {%0, %1}, %2;" : "=f"(f.x), "=f"(f.y) : "l"(v));
    return f;
}

/* -------------------------------------------------------------------- init */
__global__ void k_init(const float* __restrict__ ph0,
                       float* __restrict__ h0, float* __restrict__ e0) {
    int i = blockIdx.x * blockDim.x + threadIdx.x;
    if (i < B * HID) {
        h0[i] = ph0[i & (HID - 1)];
        e0[i] = 0.f;
    }
}

/* ------------------------------------------------- encoder GEMV (B=8, K=2048) */
/* out[b][o] = act( sum_k in[b][k] * W[o][k] + bias[o] ),  warp per output o.  */
__global__ __launch_bounds__(256) void k_gemv8(
    const float* __restrict__ in, const float* __restrict__ W,
    const float* __restrict__ bias, float* __restrict__ out,
    int K, int O, int act)
{
    __shared__ __align__(16) float sh[B * 1024];
    int tid  = threadIdx.x;
    int lane = tid & 31;
    int o    = blockIdx.x * 8 + (tid >> 5);
    const float* wrow = W + (size_t)o * K;

    float acc[B];
#pragma unroll
    for (int b = 0; b < B; b++) acc[b] = 0.f;

    for (int k0 = 0; k0 < K; k0 += 1024) {
        __syncthreads();
#pragma unroll
        for (int b = 0; b < B; b++)
            for (int k = tid; k < 1024; k += 256)
                sh[b * 1024 + k] = in[b * K + k0 + k];
        __syncthreads();
        for (int k = lane; k < 1024; k += 32) {
            float wv = wrow[k0 + k];
#pragma unroll
            for (int b = 0; b < B; b++) acc[b] += wv * sh[b * 1024 + k];
        }
    }
#pragma unroll
    for (int b = 0; b < B; b++)
#pragma unroll
        for (int off = 16; off; off >>= 1)
            acc[b] += __shfl_xor_sync(0xffffffffu, acc[b], off);

    if (lane < B) {
        float v = 0.f;
#pragma unroll
        for (int b = 0; b < B; b++) if (lane == b) v = acc[b];
        v += bias[o];
        if (act) v = tanhf(v);
        out[lane * O + o] = v;
    }
}

/* ------------------------------------------------------------------- GRU cell */
/* warp per hidden unit j: computes all 6 dots (i_r,i_z,i_n,h_r,h_z,h_n) for 8 b */
__global__ __launch_bounds__(256) void k_gru(
    const float* __restrict__ e, const float* __restrict__ hprev,
    const float* __restrict__ w_ih, const float* __restrict__ b_ih,
    const float* __restrict__ w_hh, const float* __restrict__ b_hh,
    float* __restrict__ hnew)
{
    __shared__ float esh[B * EMB];
    __shared__ float hsh[B * HID];
    int tid = threadIdx.x;
    for (int i = tid; i < B * EMB; i += 256) { esh[i] = e[i]; hsh[i] = hprev[i]; }
    __syncthreads();

    int j    = blockIdx.x * 8 + (tid >> 5);
    int lane = tid & 31;
    const float* wi0 = w_ih + (size_t)j * HID;
    const float* wi1 = w_ih + (size_t)(j + HID) * HID;
    const float* wi2 = w_ih + (size_t)(j + 2 * HID) * HID;
    const float* wh0 = w_hh + (size_t)j * HID;
    const float* wh1 = w_hh + (size_t)(j + HID) * HID;
    const float* wh2 = w_hh + (size_t)(j + 2 * HID) * HID;

    float a[6][B];
#pragma unroll
    for (int r = 0; r < 6; r++)
#pragma unroll
        for (int b = 0; b < B; b++) a[r][b] = 0.f;

    for (int k = lane; k < HID; k += 32) {
        float v0 = wi0[k], v1 = wi1[k], v2 = wi2[k];
        float v3 = wh0[k], v4 = wh1[k], v5 = wh2[k];
#pragma unroll
        for (int b = 0; b < B; b++) {
            float ev = esh[b * HID + k], hv = hsh[b * HID + k];
            a[0][b] += v0 * ev;  a[1][b] += v1 * ev;  a[2][b] += v2 * ev;
            a[3][b] += v3 * hv;  a[4][b] += v4 * hv;  a[5][b] += v5 * hv;
        }
    }
#pragma unroll
    for (int r = 0; r < 6; r++)
#pragma unroll
        for (int b = 0; b < B; b++)
#pragma unroll
            for (int off = 16; off; off >>= 1)
                a[r][b] += __shfl_xor_sync(0xffffffffu, a[r][b], off);

    if (lane < B) {
        float ir = 0, iz = 0, inn = 0, hr = 0, hz = 0, hn = 0;
#pragma unroll
        for (int b = 0; b < B; b++) if (lane == b) {
            ir = a[0][b]; iz = a[1][b]; inn = a[2][b];
            hr = a[3][b]; hz = a[4][b]; hn  = a[5][b];
        }
        ir  += b_ih[j];            hr += b_hh[j];
        iz  += b_ih[j + HID];      hz += b_hh[j + HID];
        inn += b_ih[j + 2 * HID];  hn += b_hh[j + 2 * HID];
        float r = 1.f / (1.f + __expf(-(ir + hr)));
        float z = 1.f / (1.f + __expf(-(iz + hz)));
        float n = tanhf(inn + r * hn);
        hnew[lane * HID + j] = (1.f - z) * n + z * hsh[lane * HID + j];
    }
}

/* ---------------------------------------------------------- logits + exp(+g) */
/* block handles 128 contiguous v rows; warp processes 4 rows at a time with     */
/* packed f32x2 FMAs.  Writes unnormalized u into out[b][t][v]; per-block S.     */
__global__ __launch_bounds__(256, 2) void k_logits(
    const float* __restrict__ h, const float* __restrict__ emb_out,
    const float* __restrict__ gt, float* __restrict__ uo,
    float* __restrict__ Spart)
{
    __shared__ __align__(16) float hsh[B * HID];
    __shared__ float gsh[B][VB_LOG];
    __shared__ float ush[B][VB_LOG];
    __shared__ float ssh[B];
    int tid   = threadIdx.x;
    int vbase = blockIdx.x * VB_LOG;

    for (int i = tid; i < B * HID; i += 256) hsh[i] = h[i];
    for (int i = tid; i < B * VB_LOG; i += 256) {
        int b = i >> 7, vv = i & (VB_LOG - 1);
        gsh[b][vv] = gt[b * VOC + vbase + vv];
    }
    if (tid < B) ssh[tid] = 0.f;
    __syncthreads();

    int w = tid >> 5, lane = tid & 31;
    float ssum = 0.f;

#pragma unroll 1
    for (int grp = 0; grp < 4; grp++) {
        int vl = w * 16 + grp * 4;
        const float* r = emb_out + (size_t)(vbase + vl) * HID;

        ull acc[4][B];
#pragma unroll
        for (int jj = 0; jj < 4; jj++)
#pragma unroll
            for (int b = 0; b < B; b++) acc[jj][b] = 0ULL;

#pragma unroll
        for (int i = 0; i < 8; i++) {
            int kk = i * 64 + lane * 2;
            ull w0 = *(const ull*)(r + kk);
            ull w1 = *(const ull*)(r + HID + kk);
            ull w2 = *(const ull*)(r + 2 * HID + kk);
            ull w3 = *(const ull*)(r + 3 * HID + kk);
#pragma unroll
            for (int b = 0; b < B; b++) {
                ull hb = *(const ull*)(hsh + b * HID + kk);
                acc[0][b] = ffma2(w0, hb, acc[0][b]);
                acc[1][b] = ffma2(w1, hb, acc[1][b]);
                acc[2][b] = ffma2(w2, hb, acc[2][b]);
                acc[3][b] = ffma2(w3, hb, acc[3][b]);
            }
        }
#pragma unroll
        for (int jj = 0; jj < 4; jj++) {
#pragma unroll
            for (int b = 0; b < B; b++) {
                float2 f = unpack2(acc[jj][b]);
                float s = f.x + f.y;
#pragma unroll
                for (int off = 16; off; off >>= 1)
                    s += __shfl_xor_sync(0xffffffffu, s, off);
                if (lane == b) {
                    float u = __expf(s + gsh[b][vl + jj]);
                    ush[b][vl + jj] = u;
                    ssum += u;
                }
            }
        }
    }
    if (lane < B) atomicAdd(&ssh[lane], ssum);
    __syncthreads();
    for (int i = tid; i < B * VB_LOG; i += 256) {
        int b = i >> 7, vv = i & (VB_LOG - 1);
        uo[(size_t)b * OUT_BT + vbase + vv] = ush[b][vv];
    }
    if (tid < B) Spart[blockIdx.x * B + tid] = ssh[tid];
}

/* ------------------------------------------- e projection: P = u @ emb_in */
/* block handles a chunk of v rows, accumulates [8 x 512] partial in regs.  */
__global__ __launch_bounds__(256) void k_eproj(
    const float* __restrict__ u, const float* __restrict__ emb_in,
    float* __restrict__ Ppart)
{
    __shared__ ull ush2[B][VCH_EP + 1];
    int blk = blockIdx.x;
    int v0  = blk * VCH_EP;
    int cnt = min(VCH_EP, VOC - v0);
    int tid = threadIdx.x;

#pragma unroll
    for (int b = 0; b < B; b++)
        for (int vv = tid; vv < cnt; vv += 256) {
            float uv = u[(size_t)b * OUT_BT + v0 + vv];
            ush2[b][vv] = pack2(uv, uv);
        }
    __syncthreads();

    int c = tid * 2;
    const float* base = emb_in + (size_t)v0 * EMB + c;
    ull acc[B];
#pragma unroll
    for (int b = 0; b < B; b++) acc[b] = 0ULL;

    int vv = 0;
    for (; vv + 4 <= cnt; vv += 4) {
        ull w0 = *(const ull*)(base + (size_t)(vv + 0) * EMB);
        ull w1 = *(const ull*)(base + (size_t)(vv + 1) * EMB);
        ull w2 = *(const ull*)(base + (size_t)(vv + 2) * EMB);
        ull w3 = *(const ull*)(base + (size_t)(vv + 3) * EMB);
#pragma unroll
        for (int b = 0; b < B; b++) {
            acc[b] = ffma2(ush2[b][vv + 0], w0, acc[b]);
            acc[b] = ffma2(ush2[b][vv + 1], w1, acc[b]);
            acc[b] = ffma2(ush2[b][vv + 2], w2, acc[b]);
            acc[b] = ffma2(ush2[b][vv + 3], w3, acc[b]);
        }
    }
    for (; vv < cnt; vv++) {
        ull w0 = *(const ull*)(base + (size_t)vv * EMB);
#pragma unroll
        for (int b = 0; b < B; b++) acc[b] = ffma2(ush2[b][vv], w0, acc[b]);
    }
    ull* P = (ull*)(Ppart + (size_t)blk * (B * EMB));
#pragma unroll
    for (int b = 0; b < B; b++) P[b * 256 + tid] = acc[b];
}

/* ----------------------------- reduce partials -> e_state, store S for norm */
__global__ __launch_bounds__(256) void k_reduce(
    const float* __restrict__ Ppart, const float* __restrict__ Spart,
    const float* __restrict__ img, float* __restrict__ e_out,
    float* __restrict__ S_out)
{
    __shared__ float sS[B];
    int tid = threadIdx.x, w = tid >> 5, lane = tid & 31;
    if (w < B) {
        float s = 0.f;
        for (int p = lane; p < NB_LOG; p += 32) s += Spart[p * B + w];
#pragma unroll
        for (int off = 16; off; off >>= 1)
            s += __shfl_xor_sync(0xffffffffu, s, off);
        if (lane == 0) sS[w] = s;
    }
    __syncthreads();

    int idx = blockIdx.x * 256 + tid;              /* 16 blocks -> 4096 */
    float s = 0.f;
#pragma unroll 4
    for (int p = 0; p < NB_EP; p++) s += Ppart[p * (B * EMB) + idx];
    int b = idx >> 9;
    e_out[idx] = __fdividef(s, sS[b]) * img[idx];
    if (blockIdx.x == 0 && tid < B) S_out[tid] = sS[tid];
}

/* -------------------------------------------------- final softmax normalize */
__global__ void k_norm(float* __restrict__ out, const float* __restrict__ S) {
    size_t idx = (size_t)blockIdx.x * blockDim.x + threadIdx.x;
    if (idx < (size_t)B * OUT_BT) {
        int b = (int)(idx / OUT_BT);
        int t = (int)(idx / VOC) & (TLEN - 1);
        out[idx] = __fdividef(out[idx], __ldg(&S[t * B + b]));
    }
}

/* ------------------------------------------------------------------ driver */
extern "C" void kernel_launch(void* const* d_in, const int* in_sizes, int n_in,
                              void* d_out, int out_size) {
    (void)in_sizes; (void)n_in; (void)out_size;
    const float* x       = (const float*)d_in[0];
    const float* enc_w   = (const float*)d_in[1];
    const float* enc_b   = (const float*)d_in[2];
    const float* out_w   = (const float*)d_in[3];
    const float* out_b   = (const float*)d_in[4];
    const float* emb_out = (const float*)d_in[5];
    const float* emb_in  = (const float*)d_in[6];
    const float* ph0     = (const float*)d_in[7];
    const float* w_ih    = (const float*)d_in[8];
    const float* b_ih    = (const float*)d_in[9];
    const float* w_hh    = (const float*)d_in[10];
    const float* b_hh    = (const float*)d_in[11];
    const float* gumbel  = (const float*)d_in[12];
    float* out = (float*)d_out;

    float *p_enc0, *p_enc1, *p_img, *p_h0, *p_h1, *p_e, *p_Pp, *p_Sp, *p_S;
    cudaGetSymbolAddress((void**)&p_enc0, g_enc0);
    cudaGetSymbolAddress((void**)&p_enc1, g_enc1);
    cudaGetSymbolAddress((void**)&p_img,  g_img);
    cudaGetSymbolAddress((void**)&p_h0,   g_h0);
    cudaGetSymbolAddress((void**)&p_h1,   g_h1);
    cudaGetSymbolAddress((void**)&p_e,    g_e);
    cudaGetSymbolAddress((void**)&p_Pp,   g_Ppart);
    cudaGetSymbolAddress((void**)&p_Sp,   g_Spart);
    cudaGetSymbolAddress((void**)&p_S,    g_S);

    /* init hidden/embedding state */
    k_init<<<16, 256>>>(ph0, p_h0, p_e);

    /* encoder: 2 tanh layers + projection to img_feats */
    k_gemv8<<<DIM / 8, 256>>>(x,      enc_w,               enc_b,       p_enc0, DIM, DIM, 1);
    k_gemv8<<<DIM / 8, 256>>>(p_enc0, enc_w + DIM * DIM,   enc_b + DIM, p_enc1, DIM, DIM, 1);
    k_gemv8<<<EMB / 8, 256>>>(p_enc1, out_w,               out_b,       p_img,  DIM, EMB, 0);

    float* hbuf[2] = { p_h0, p_h1 };
    for (int t = 0; t < TLEN; t++) {
        float* hcur = hbuf[t & 1];
        float* hnxt = hbuf[(t + 1) & 1];
        k_gru<<<HID / 8, 256>>>(p_e, hcur, w_ih, b_ih, w_hh, b_hh, hnxt);
        k_logits<<<NB_LOG, 256>>>(hnxt, emb_out, gumbel + (size_t)t * B * VOC,
                                  out + (size_t)t * VOC, p_Sp);
        k_eproj<<<NB_EP, 256>>>(out + (size_t)t * VOC, emb_in, p_Pp);
        k_reduce<<<16, 256>>>(p_Pp, p_Sp, p_img, p_e, p_S + t * B);
    }
    k_norm<<<(B * OUT_BT + 255) / 256, 256>>>(out, p_S);
}

// round 3
// speedup vs baseline: 1.8680x; 1.8680x over previous
#include <cuda_runtime.h>
#include <cuda_bf16.h>

typedef unsigned long long ull;

#define B       8
#define DIM     2048
#define EMB     512
#define HID     512
#define VOC     32000
#define TLEN    32
#define OUT_BT  (TLEN * VOC)

#define TILE_V    112
#define GRID_MAIN 286                 /* ceil(32000/112) */
#define SM_HSH    16384               /* h staging: 8x512 f32 */
#define SM_W      (112 * 132 * 4)     /* W tile, 128+4 pad floats per row */
#define SM_USH    (112 * 8 * 8)       /* u packed (u,u) per (row,b) */
#define SMEM_MAIN (SM_HSH + SM_W + SM_USH + 32)

/* ------------------------------------------------------------------ scratch */
__device__ __align__(16) float g_enc0 [B * DIM];
__device__ __align__(16) float g_enc1 [B * DIM];
__device__ __align__(16) float g_img  [B * EMB];
__device__ __align__(16) float g_h0   [B * HID];
__device__ __align__(16) float g_h1   [B * HID];
__device__ __align__(16) float g_Pacc [2 * B * EMB];
__device__ __align__(16) float g_S    [TLEN * B];
__device__ __align__(16) float g_Sone [B];

/* ------------------------------------------------------------------ helpers */
__device__ __forceinline__ ull ffma2(ull a, ull b, ull c) {
    ull d;
    asm("fma.rn.f32x2 %0, %1, %2, %3;" : "=l"(d) : "l"(a), "l"(b), "l"(c));
    return d;
}
__device__ __forceinline__ ull pack2(float x, float y) {
    ull r;
    asm("mov.b64 %0, {%1, %2};" : "=l"(r) : "f"(x), "f"(y));
    return r;
}
__device__ __forceinline__ float2 unpack2(ull v) {
    float2 f;
    asm("mov.b64 {%0, %1}, %2;" : "=f"(f.x), "=f"(f.y) : "l"(v));
    return f;
}

/* -------------------------------------------------------------------- init */
__global__ void k_init(const float* __restrict__ ph0,
                       float* __restrict__ h0, float* __restrict__ Pacc,
                       float* __restrict__ S, float* __restrict__ Sone) {
    int i = blockIdx.x * blockDim.x + threadIdx.x;
    if (i < B * HID) {
        h0[i] = ph0[i & (HID - 1)];
    } else if (i < B * HID + 2 * B * EMB) {
        Pacc[i - B * HID] = 0.f;
    } else if (i < B * HID + 2 * B * EMB + TLEN * B) {
        S[i - B * HID - 2 * B * EMB] = 0.f;
    } else if (i < B * HID + 2 * B * EMB + TLEN * B + B) {
        Sone[i - B * HID - 2 * B * EMB - TLEN * B] = 1.f;
    }
}

/* -------------------------------------- encoder GEMV (B=8, K=2048), f32x2 */
__global__ __launch_bounds__(256) void k_gemv8(
    const float* __restrict__ in, const float* __restrict__ W,
    const float* __restrict__ bias, float* __restrict__ out,
    int K, int O, int act)
{
    __shared__ __align__(16) float sh[B * 1024];
    int tid  = threadIdx.x;
    int lane = tid & 31;
    int o    = blockIdx.x * 8 + (tid >> 5);
    const float* wrow = W + (size_t)o * K;

    ull acc[B];
#pragma unroll
    for (int b = 0; b < B; b++) acc[b] = 0ULL;

    for (int k0 = 0; k0 < K; k0 += 1024) {
        __syncthreads();
#pragma unroll
        for (int b = 0; b < B; b++) {
            int k = tid * 4;
            *(float4*)(sh + b * 1024 + k) = *(const float4*)(in + (size_t)b * K + k0 + k);
        }
        __syncthreads();
#pragma unroll
        for (int kk = 0; kk < 1024; kk += 128) {
            int k = kk + lane * 4;
            ulonglong2 w2 = *(const ulonglong2*)(wrow + k0 + k);
#pragma unroll
            for (int b = 0; b < B; b++) {
                ulonglong2 i2 = *(const ulonglong2*)(sh + b * 1024 + k);
                acc[b] = ffma2(w2.x, i2.x, acc[b]);
                acc[b] = ffma2(w2.y, i2.y, acc[b]);
            }
        }
    }
    float s[B];
#pragma unroll
    for (int b = 0; b < B; b++) {
        float2 f = unpack2(acc[b]);
        s[b] = f.x + f.y;
#pragma unroll
        for (int off = 16; off; off >>= 1)
            s[b] += __shfl_xor_sync(0xffffffffu, s[b], off);
    }
    if (lane < B) {
        float v = 0.f;
#pragma unroll
        for (int b = 0; b < B; b++) if (lane == b) v = s[b];
        v += bias[o];
        if (act) v = tanhf(v);
        out[lane * O + o] = v;
    }
}

/* ---------------------------------------------- GRU + e-finalize + P-zero */
__global__ __launch_bounds__(256) void k_gru2(
    const float* __restrict__ Pread, float* __restrict__ Pzero,
    const float* __restrict__ Sprev, const float* __restrict__ img,
    const float* __restrict__ hprev,
    const float* __restrict__ w_ih, const float* __restrict__ b_ih,
    const float* __restrict__ w_hh, const float* __restrict__ b_hh,
    float* __restrict__ hnew)
{
    __shared__ float esh[B * EMB];
    __shared__ float hsh[B * HID];
    int tid = threadIdx.x;
#pragma unroll
    for (int ii = 0; ii < (B * EMB) / 256; ii++) {
        int i = ii * 256 + tid;
        int b = i >> 9;
        esh[i] = __fdividef(Pread[i], Sprev[b]) * img[i];
        hsh[i] = hprev[i];
    }
    /* zero this step's accumulator slice (4096 / 64 blocks = 64 each) */
    if (tid < 64) Pzero[blockIdx.x * 64 + tid] = 0.f;
    __syncthreads();

    int j    = blockIdx.x * 8 + (tid >> 5);
    int lane = tid & 31;
    const float* wi0 = w_ih + (size_t)j * HID;
    const float* wi1 = w_ih + (size_t)(j + HID) * HID;
    const float* wi2 = w_ih + (size_t)(j + 2 * HID) * HID;
    const float* wh0 = w_hh + (size_t)j * HID;
    const float* wh1 = w_hh + (size_t)(j + HID) * HID;
    const float* wh2 = w_hh + (size_t)(j + 2 * HID) * HID;

    float a[6][B];
#pragma unroll
    for (int r = 0; r < 6; r++)
#pragma unroll
        for (int b = 0; b < B; b++) a[r][b] = 0.f;

#pragma unroll 4
    for (int k = lane; k < HID; k += 32) {
        float v0 = wi0[k], v1 = wi1[k], v2 = wi2[k];
        float v3 = wh0[k], v4 = wh1[k], v5 = wh2[k];
#pragma unroll
        for (int b = 0; b < B; b++) {
            float ev = esh[b * HID + k], hv = hsh[b * HID + k];
            a[0][b] += v0 * ev;  a[1][b] += v1 * ev;  a[2][b] += v2 * ev;
            a[3][b] += v3 * hv;  a[4][b] += v4 * hv;  a[5][b] += v5 * hv;
        }
    }
#pragma unroll
    for (int r = 0; r < 6; r++)
#pragma unroll
        for (int b = 0; b < B; b++)
#pragma unroll
            for (int off = 16; off; off >>= 1)
                a[r][b] += __shfl_xor_sync(0xffffffffu, a[r][b], off);

    if (lane < B) {
        float ir = 0, iz = 0, inn = 0, hr = 0, hz = 0, hn = 0;
#pragma unroll
        for (int b = 0; b < B; b++) if (lane == b) {
            ir = a[0][b]; iz = a[1][b]; inn = a[2][b];
            hr = a[3][b]; hz = a[4][b]; hn  = a[5][b];
        }
        ir  += b_ih[j];            hr += b_hh[j];
        iz  += b_ih[j + HID];      hz += b_hh[j + HID];
        inn += b_ih[j + 2 * HID];  hn += b_hh[j + 2 * HID];
        float r = 1.f / (1.f + __expf(-(ir + hr)));
        float z = 1.f / (1.f + __expf(-(iz + hz)));
        float n = tanhf(inn + r * hn);
        hnew[lane * HID + j] = (1.f - z) * n + z * hsh[lane * HID + j];
    }
}

/* ------------------------- fused: logits -> exp -> u store -> P partials */
__global__ __launch_bounds__(256, 2) void k_main(
    const float* __restrict__ h, const float* __restrict__ emb_out,
    const float* __restrict__ emb_in, const float* __restrict__ gt,
    float* __restrict__ uo, float* __restrict__ Pacc,
    float* __restrict__ Sacc)
{
    extern __shared__ __align__(16) char dsm[];
    float* hsh  = (float*)dsm;
    float* smW  = (float*)(dsm + SM_HSH);
    ull*   ushp = (ull*)  (dsm + SM_HSH + SM_W);
    float* ssh  = (float*)(dsm + SM_HSH + SM_W + SM_USH);

    int tid  = threadIdx.x;
    int wid  = tid >> 5;
    int lane = tid & 31;
    int v0   = blockIdx.x * TILE_V;

#pragma unroll
    for (int ii = 0; ii < (B * HID) / 256; ii++)
        hsh[ii * 256 + tid] = h[ii * 256 + tid];
    if (tid < B) ssh[tid] = 0.f;

    /* ---- phase A: logits for TILE_V rows, all 8 batches ---- */
    int rowl = wid * 14 + (lane >> 1);          /* lanes 28-31 duplicate */
    if (rowl > TILE_V - 1) rowl = TILE_V - 1;
    int ks   = lane & 1;                        /* 2-way K split */

    ull acc[B];
#pragma unroll
    for (int b = 0; b < B; b++) acc[b] = 0ULL;

    for (int c = 0; c < 4; c++) {               /* K chunks of 128 */
        __syncthreads();
        /* stage W tile chunk: warp w loads rows w, w+8, ... coalesced */
#pragma unroll
        for (int rr = 0; rr < 14; rr++) {
            int row = wid + rr * 8;
            int v   = v0 + row;
            int vc  = v < VOC ? v : VOC - 1;
            float4 t4 = *(const float4*)(emb_out + (size_t)vc * HID + c * 128 + lane * 4);
            *(float4*)(smW + row * 132 + lane * 4) = t4;
        }
        __syncthreads();

        const float* wrow  = smW + rowl * 132 + ks * 64;
        const float* hbase = hsh + c * 128 + ks * 64;
#pragma unroll 4
        for (int i = 0; i < 16; i++) {
            ulonglong2 ww = *(const ulonglong2*)(wrow + i * 4);
#pragma unroll
            for (int b = 0; b < B; b++) {
                ulonglong2 hh = *(const ulonglong2*)(hbase + b * HID + i * 4);
                acc[b] = ffma2(ww.x, hh.x, acc[b]);
                acc[b] = ffma2(ww.y, hh.y, acc[b]);
            }
        }
    }

    /* pair-reduce the 2-way K split */
    float s[B];
#pragma unroll
    for (int b = 0; b < B; b++) {
        float2 f = unpack2(acc[b]);
        float t = f.x + f.y;
        t += __shfl_xor_sync(0xffffffffu, t, 1);
        s[b] = t;
    }

    int par = lane & 1;                 /* even lane: b0-3, odd: b4-7 */
    float ss[4] = {0.f, 0.f, 0.f, 0.f};
    int v = v0 + rowl;
    if (lane < 28) {
#pragma unroll
        for (int jj = 0; jj < 4; jj++) {
            int b = par * 4 + jj;
            float u = 0.f;
            if (v < VOC) {
                u = __expf(s[b] + gt[(size_t)b * VOC + v]);
                uo[(size_t)b * OUT_BT + v] = u;
            }
            ushp[rowl * 8 + b] = pack2(u, u);
            ss[jj] = u;
        }
    }
    /* parity-preserving butterfly: lane0 -> b0-3 totals, lane1 -> b4-7 */
#pragma unroll
    for (int off = 16; off >= 2; off >>= 1)
#pragma unroll
        for (int jj = 0; jj < 4; jj++)
            ss[jj] += __shfl_xor_sync(0xffffffffu, ss[jj], off);
    if (lane < 2)
#pragma unroll
        for (int jj = 0; jj < 4; jj++)
            atomicAdd(&ssh[lane * 4 + jj], ss[jj]);

    __syncthreads();
    if (tid < B) atomicAdd(&Sacc[tid], ssh[tid]);

    /* ---- phase B: P partial += u(rows) @ emb_in(rows) ---- */
    int q  = tid & 127;                 /* col quad: cols 4q..4q+3 */
    int h2 = tid >> 7;                  /* row half */
    const float* wbase = emb_in + 4 * q;

    ull pa[B][2];
#pragma unroll
    for (int b = 0; b < B; b++) { pa[b][0] = 0ULL; pa[b][1] = 0ULL; }

    int r0 = h2 * 56;
#pragma unroll 2
    for (int r = r0; r < r0 + 56; r++) {
        int vv = v0 + r;
        int vc = vv < VOC ? vv : VOC - 1;      /* masked rows have u==0 */
        ulonglong2 ww = *(const ulonglong2*)(wbase + (size_t)vc * EMB);
#pragma unroll
        for (int b = 0; b < B; b++) {
            ull ub = ushp[r * 8 + b];
            pa[b][0] = ffma2(ub, ww.x, pa[b][0]);
            pa[b][1] = ffma2(ub, ww.y, pa[b][1]);
        }
    }
#pragma unroll
    for (int b = 0; b < B; b++) {
        float2 f0 = unpack2(pa[b][0]);
        float2 f1 = unpack2(pa[b][1]);
        float* dst = Pacc + b * EMB + 4 * q;
        atomicAdd(dst + 0, f0.x);
        atomicAdd(dst + 1, f0.y);
        atomicAdd(dst + 2, f1.x);
        atomicAdd(dst + 3, f1.y);
    }
}

/* -------------------------------------------------- final softmax normalize */
__global__ void k_norm(float* __restrict__ out, const float* __restrict__ S) {
    size_t idx = (size_t)blockIdx.x * blockDim.x + threadIdx.x;
    if (idx < (size_t)B * OUT_BT) {
        int b = (int)(idx / OUT_BT);
        int t = (int)(idx / VOC) & (TLEN - 1);
        out[idx] = __fdividef(out[idx], __ldg(&S[t * B + b]));
    }
}

/* ------------------------------------------------------------------ driver */
extern "C" void kernel_launch(void* const* d_in, const int* in_sizes, int n_in,
                              void* d_out, int out_size) {
    (void)in_sizes; (void)n_in; (void)out_size;
    const float* x       = (const float*)d_in[0];
    const float* enc_w   = (const float*)d_in[1];
    const float* enc_b   = (const float*)d_in[2];
    const float* out_w   = (const float*)d_in[3];
    const float* out_b   = (const float*)d_in[4];
    const float* emb_out = (const float*)d_in[5];
    const float* emb_in  = (const float*)d_in[6];
    const float* ph0     = (const float*)d_in[7];
    const float* w_ih    = (const float*)d_in[8];
    const float* b_ih    = (const float*)d_in[9];
    const float* w_hh    = (const float*)d_in[10];
    const float* b_hh    = (const float*)d_in[11];
    const float* gumbel  = (const float*)d_in[12];
    float* out = (float*)d_out;

    float *p_enc0, *p_enc1, *p_img, *p_h0, *p_h1, *p_Pacc, *p_S, *p_Sone;
    cudaGetSymbolAddress((void**)&p_enc0, g_enc0);
    cudaGetSymbolAddress((void**)&p_enc1, g_enc1);
    cudaGetSymbolAddress((void**)&p_img,  g_img);
    cudaGetSymbolAddress((void**)&p_h0,   g_h0);
    cudaGetSymbolAddress((void**)&p_h1,   g_h1);
    cudaGetSymbolAddress((void**)&p_Pacc, g_Pacc);
    cudaGetSymbolAddress((void**)&p_S,    g_S);
    cudaGetSymbolAddress((void**)&p_Sone, g_Sone);

    cudaFuncSetAttribute(k_main, cudaFuncAttributeMaxDynamicSharedMemorySize,
                         SMEM_MAIN);

    int init_n = B * HID + 2 * B * EMB + TLEN * B + B;
    k_init<<<(init_n + 255) / 256, 256>>>(ph0, p_h0, p_Pacc, p_S, p_Sone);

    k_gemv8<<<DIM / 8, 256>>>(x,      enc_w,             enc_b,       p_enc0, DIM, DIM, 1);
    k_gemv8<<<DIM / 8, 256>>>(p_enc0, enc_w + DIM * DIM, enc_b + DIM, p_enc1, DIM, DIM, 1);
    k_gemv8<<<EMB / 8, 256>>>(p_enc1, out_w,             out_b,       p_img,  DIM, EMB, 0);

    float* hbuf[2] = { p_h0, p_h1 };
    for (int t = 0; t < TLEN; t++) {
        const float* Sprev = (t == 0) ? p_Sone : (p_S + (t - 1) * B);
        float* Pread = p_Pacc + ((t + 1) & 1) * (B * EMB);
        float* Pwr   = p_Pacc + (t & 1) * (B * EMB);
        k_gru2<<<HID / 8, 256>>>(Pread, Pwr, Sprev, p_img, hbuf[t & 1],
                                 w_ih, b_ih, w_hh, b_hh, hbuf[(t + 1) & 1]);
        k_main<<<GRID_MAIN, 256, SMEM_MAIN>>>(hbuf[(t + 1) & 1], emb_out, emb_in,
                                              gumbel + (size_t)t * B * VOC,
                                              out + (size_t)t * VOC,
                                              Pwr, p_S + t * B);
    }
    k_norm<<<(B * OUT_BT + 255) / 256, 256>>>(out, p_S);
}

// round 4
// speedup vs baseline: 1.9753x; 1.0574x over previous
#include <cuda_runtime.h>
#include <cuda_bf16.h>

typedef unsigned long long ull;

#define B       8
#define DIM     2048
#define EMB     512
#define HID     512
#define VOC     32000
#define TLEN    32
#define OUT_BT  (TLEN * VOC)

#define TILE_V    112
#define NB_MAIN   286                 /* ceil(32000/112) */
#define SM_HSH    16384               /* h staging: 8x512 f32 (reused as P-red) */
#define SM_W      (112 * 132 * 4)     /* W tile, 128+4 pad floats per row */
#define SM_USH    (112 * 8 * 8)       /* u packed (u,u) per (row,b) */
#define SMEM_MAIN (SM_HSH + SM_W + SM_USH + 64)

/* ------------------------------------------------------------------ scratch */
__device__ __align__(16) float g_enc0 [B * DIM];
__device__ __align__(16) float g_enc1 [B * DIM];
__device__ __align__(16) float g_img  [B * EMB];
__device__ __align__(16) float g_h0   [B * HID];
__device__ __align__(16) float g_h1   [B * HID];
__device__ __align__(16) float g_e    [B * EMB];
__device__ __align__(16) float g_Ppart[NB_MAIN * B * EMB];
__device__ __align__(16) float g_Spart[NB_MAIN * B];
__device__ __align__(16) float g_S    [TLEN * B];

/* ------------------------------------------------------------------ helpers */
__device__ __forceinline__ ull ffma2(ull a, ull b, ull c) {
    ull d;
    asm("fma.rn.f32x2 %0, %1, %2, %3;" : "=l"(d) : "l"(a), "l"(b), "l"(c));
    return d;
}
__device__ __forceinline__ ull pack2(float x, float y) {
    ull r;
    asm("mov.b64 %0, {%1, %2};" : "=l"(r) : "f"(x), "f"(y));
    return r;
}
__device__ __forceinline__ float2 unpack2(ull v) {
    float2 f;
    asm("mov.b64 {%0, %1}, %2;" : "=f"(f.x), "=f"(f.y) : "l"(v));
    return f;
}

/* -------------------------------------------------------------------- init */
__global__ void k_init(const float* __restrict__ ph0,
                       float* __restrict__ h0, float* __restrict__ e0) {
    int i = blockIdx.x * blockDim.x + threadIdx.x;
    if (i < B * HID) {
        h0[i] = ph0[i & (HID - 1)];
        e0[i] = 0.f;
    }
}

/* -------------------------------------- encoder GEMV (B=8, K=2048), f32x2 */
__global__ __launch_bounds__(256) void k_gemv8(
    const float* __restrict__ in, const float* __restrict__ W,
    const float* __restrict__ bias, float* __restrict__ out,
    int K, int O, int act)
{
    __shared__ __align__(16) float sh[B * 1024];
    int tid  = threadIdx.x;
    int lane = tid & 31;
    int o    = blockIdx.x * 8 + (tid >> 5);
    const float* wrow = W + (size_t)o * K;

    ull acc[B];
#pragma unroll
    for (int b = 0; b < B; b++) acc[b] = 0ULL;

    for (int k0 = 0; k0 < K; k0 += 1024) {
        __syncthreads();
#pragma unroll
        for (int b = 0; b < B; b++) {
            int k = tid * 4;
            *(float4*)(sh + b * 1024 + k) = *(const float4*)(in + (size_t)b * K + k0 + k);
        }
        __syncthreads();
#pragma unroll
        for (int kk = 0; kk < 1024; kk += 128) {
            int k = kk + lane * 4;
            ulonglong2 w2 = *(const ulonglong2*)(wrow + k0 + k);
#pragma unroll
            for (int b = 0; b < B; b++) {
                ulonglong2 i2 = *(const ulonglong2*)(sh + b * 1024 + k);
                acc[b] = ffma2(w2.x, i2.x, acc[b]);
                acc[b] = ffma2(w2.y, i2.y, acc[b]);
            }
        }
    }
    float s[B];
#pragma unroll
    for (int b = 0; b < B; b++) {
        float2 f = unpack2(acc[b]);
        s[b] = f.x + f.y;
#pragma unroll
        for (int off = 16; off; off >>= 1)
            s[b] += __shfl_xor_sync(0xffffffffu, s[b], off);
    }
    if (lane < B) {
        float v = 0.f;
#pragma unroll
        for (int b = 0; b < B; b++) if (lane == b) v = s[b];
        v += bias[o];
        if (act) v = tanhf(v);
        out[lane * O + o] = v;
    }
}

/* ----------------- reduce P partials + S sums -> e state (and S for norm) */
__global__ __launch_bounds__(256) void k_reduce(
    const float* __restrict__ Ppart, const float* __restrict__ Spart,
    const float* __restrict__ img, float* __restrict__ e_out,
    float* __restrict__ S_out)
{
    __shared__ float sS[B];
    int tid = threadIdx.x, w = tid >> 5, lane = tid & 31;
    if (w < B) {
        float s = 0.f;
        for (int p = lane; p < NB_MAIN; p += 32) s += Spart[p * B + w];
#pragma unroll
        for (int off = 16; off; off >>= 1)
            s += __shfl_xor_sync(0xffffffffu, s, off);
        if (lane == 0) sS[w] = s;
    }
    __syncthreads();

    int idx = blockIdx.x * 256 + tid;              /* 16 blocks -> 4096 */
    float a0 = 0.f, a1 = 0.f, a2 = 0.f, a3 = 0.f;
    int p = 0;
#pragma unroll 2
    for (; p + 4 <= NB_MAIN; p += 4) {
        a0 += Ppart[(p + 0) * (B * EMB) + idx];
        a1 += Ppart[(p + 1) * (B * EMB) + idx];
        a2 += Ppart[(p + 2) * (B * EMB) + idx];
        a3 += Ppart[(p + 3) * (B * EMB) + idx];
    }
    for (; p < NB_MAIN; p++) a0 += Ppart[p * (B * EMB) + idx];
    float s = (a0 + a1) + (a2 + a3);
    int b = idx >> 9;
    e_out[idx] = __fdividef(s, sS[b]) * img[idx];
    if (blockIdx.x == 0 && tid < B) S_out[tid] = sS[tid];
}

/* ------------------------------------------------------------------- GRU */
__global__ __launch_bounds__(256) void k_gru2(
    const float* __restrict__ e, const float* __restrict__ hprev,
    const float* __restrict__ w_ih, const float* __restrict__ b_ih,
    const float* __restrict__ w_hh, const float* __restrict__ b_hh,
    float* __restrict__ hnew)
{
    __shared__ float esh[B * EMB];
    __shared__ float hsh[B * HID];
    int tid = threadIdx.x;
#pragma unroll
    for (int ii = 0; ii < (B * EMB) / 256; ii++) {
        int i = ii * 256 + tid;
        esh[i] = e[i];
        hsh[i] = hprev[i];
    }
    __syncthreads();

    int j    = blockIdx.x * 8 + (tid >> 5);
    int lane = tid & 31;
    const float* wi0 = w_ih + (size_t)j * HID;
    const float* wi1 = w_ih + (size_t)(j + HID) * HID;
    const float* wi2 = w_ih + (size_t)(j + 2 * HID) * HID;
    const float* wh0 = w_hh + (size_t)j * HID;
    const float* wh1 = w_hh + (size_t)(j + HID) * HID;
    const float* wh2 = w_hh + (size_t)(j + 2 * HID) * HID;

    float a[6][B];
#pragma unroll
    for (int r = 0; r < 6; r++)
#pragma unroll
        for (int b = 0; b < B; b++) a[r][b] = 0.f;

#pragma unroll 4
    for (int k = lane; k < HID; k += 32) {
        float v0 = wi0[k], v1 = wi1[k], v2 = wi2[k];
        float v3 = wh0[k], v4 = wh1[k], v5 = wh2[k];
#pragma unroll
        for (int b = 0; b < B; b++) {
            float ev = esh[b * HID + k], hv = hsh[b * HID + k];
            a[0][b] += v0 * ev;  a[1][b] += v1 * ev;  a[2][b] += v2 * ev;
            a[3][b] += v3 * hv;  a[4][b] += v4 * hv;  a[5][b] += v5 * hv;
        }
    }
#pragma unroll
    for (int r = 0; r < 6; r++)
#pragma unroll
        for (int b = 0; b < B; b++)
#pragma unroll
            for (int off = 16; off; off >>= 1)
                a[r][b] += __shfl_xor_sync(0xffffffffu, a[r][b], off);

    if (lane < B) {
        float ir = 0, iz = 0, inn = 0, hr = 0, hz = 0, hn = 0;
#pragma unroll
        for (int b = 0; b < B; b++) if (lane == b) {
            ir = a[0][b]; iz = a[1][b]; inn = a[2][b];
            hr = a[3][b]; hz = a[4][b]; hn  = a[5][b];
        }
        ir  += b_ih[j];            hr += b_hh[j];
        iz  += b_ih[j + HID];      hz += b_hh[j + HID];
        inn += b_ih[j + 2 * HID];  hn += b_hh[j + 2 * HID];
        float r = 1.f / (1.f + __expf(-(ir + hr)));
        float z = 1.f / (1.f + __expf(-(iz + hz)));
        float n = tanhf(inn + r * hn);
        hnew[lane * HID + j] = (1.f - z) * n + z * hsh[lane * HID + j];
    }
}

/* ------------------- fused: logits -> exp -> u store -> P block partials */
__global__ __launch_bounds__(256, 2) void k_main(
    const float* __restrict__ h, const float* __restrict__ emb_out,
    const float* __restrict__ emb_in, const float* __restrict__ gt,
    float* __restrict__ uo, float* __restrict__ Ppart,
    float* __restrict__ Spart)
{
    extern __shared__ __align__(16) char dsm[];
    float* hsh  = (float*)dsm;                        /* reused in phase B */
    float* smW  = (float*)(dsm + SM_HSH);
    ull*   ushp = (ull*)  (dsm + SM_HSH + SM_W);
    float* ssh  = (float*)(dsm + SM_HSH + SM_W + SM_USH);

    int tid  = threadIdx.x;
    int wid  = tid >> 5;
    int lane = tid & 31;
    int v0   = blockIdx.x * TILE_V;

#pragma unroll
    for (int ii = 0; ii < (B * HID) / 256; ii++)
        hsh[ii * 256 + tid] = h[ii * 256 + tid];
    if (tid < B) ssh[tid] = 0.f;

    /* ---- phase A: logits for TILE_V rows, all 8 batches ---- */
    int rowl = wid * 14 + (lane >> 1);          /* lanes 28-31 duplicate */
    if (rowl > TILE_V - 1) rowl = TILE_V - 1;
    int ks   = lane & 1;                        /* 2-way K split */

    ull acc[B];
#pragma unroll
    for (int b = 0; b < B; b++) acc[b] = 0ULL;

    for (int c = 0; c < 4; c++) {               /* K chunks of 128 */
        __syncthreads();
#pragma unroll
        for (int rr = 0; rr < 14; rr++) {
            int row = wid + rr * 8;
            int v   = v0 + row;
            int vc  = v < VOC ? v : VOC - 1;
            float4 t4 = *(const float4*)(emb_out + (size_t)vc * HID + c * 128 + lane * 4);
            *(float4*)(smW + row * 132 + lane * 4) = t4;
        }
        __syncthreads();

        const float* wrow  = smW + rowl * 132 + ks * 64;
        const float* hbase = hsh + c * 128 + ks * 64;
#pragma unroll 4
        for (int i = 0; i < 16; i++) {
            ulonglong2 ww = *(const ulonglong2*)(wrow + i * 4);
#pragma unroll
            for (int b = 0; b < B; b++) {
                ulonglong2 hh = *(const ulonglong2*)(hbase + b * HID + i * 4);
                acc[b] = ffma2(ww.x, hh.x, acc[b]);
                acc[b] = ffma2(ww.y, hh.y, acc[b]);
            }
        }
    }

    /* pair-reduce the 2-way K split */
    float s[B];
#pragma unroll
    for (int b = 0; b < B; b++) {
        float2 f = unpack2(acc[b]);
        float t = f.x + f.y;
        t += __shfl_xor_sync(0xffffffffu, t, 1);
        s[b] = t;
    }

    int par = lane & 1;                 /* even lane: b0-3, odd: b4-7 */
    float ss[4] = {0.f, 0.f, 0.f, 0.f};
    int v = v0 + rowl;
    if (lane < 28) {
#pragma unroll
        for (int jj = 0; jj < 4; jj++) {
            int b = par * 4 + jj;
            float u = 0.f;
            if (v < VOC) {
                u = __expf(s[b] + gt[(size_t)b * VOC + v]);
                uo[(size_t)b * OUT_BT + v] = u;
            }
            ushp[rowl * 8 + b] = pack2(u, u);
            ss[jj] = u;
        }
    }
#pragma unroll
    for (int off = 16; off >= 2; off >>= 1)
#pragma unroll
        for (int jj = 0; jj < 4; jj++)
            ss[jj] += __shfl_xor_sync(0xffffffffu, ss[jj], off);
    if (lane < 2)
#pragma unroll
        for (int jj = 0; jj < 4; jj++)
            atomicAdd(&ssh[lane * 4 + jj], ss[jj]);

    __syncthreads();                    /* ushp complete, hsh dead, ssh final */
    if (tid < B) Spart[blockIdx.x * 8 + tid] = ssh[tid];

    /* ---- phase B: P partial = u(rows) @ emb_in(rows), plain stores ---- */
    int q  = tid & 127;                 /* col quad: cols 4q..4q+3 */
    int h2 = tid >> 7;                  /* row half */
    const float* wbase = emb_in + 4 * q;

    ull pa[B][2];
#pragma unroll
    for (int b = 0; b < B; b++) { pa[b][0] = 0ULL; pa[b][1] = 0ULL; }

    int r0 = h2 * 56;
    for (int rr = 0; rr < 56; rr += 4) {
        ulonglong2 w4[4];
#pragma unroll
        for (int j = 0; j < 4; j++) {
            int vv = v0 + r0 + rr + j;
            int vc = vv < VOC ? vv : VOC - 1;      /* masked rows have u==0 */
            w4[j] = *(const ulonglong2*)(wbase + (size_t)vc * EMB);
        }
#pragma unroll
        for (int j = 0; j < 4; j++) {
            int r = r0 + rr + j;
#pragma unroll
            for (int b = 0; b < B; b++) {
                ull ub = ushp[r * 8 + b];
                pa[b][0] = ffma2(ub, w4[j].x, pa[b][0]);
                pa[b][1] = ffma2(ub, w4[j].y, pa[b][1]);
            }
        }
    }

    /* combine the two row-halves through shared (reuse hsh region) */
    if (h2 == 1) {
#pragma unroll
        for (int b = 0; b < B; b++) {
            float2 f0 = unpack2(pa[b][0]);
            float2 f1 = unpack2(pa[b][1]);
            *(float4*)(hsh + b * EMB + 4 * q) = make_float4(f0.x, f0.y, f1.x, f1.y);
        }
    }
    __syncthreads();
    if (h2 == 0) {
        float* dst = Ppart + (size_t)blockIdx.x * (B * EMB);
#pragma unroll
        for (int b = 0; b < B; b++) {
            float4 o = *(const float4*)(hsh + b * EMB + 4 * q);
            float2 f0 = unpack2(pa[b][0]);
            float2 f1 = unpack2(pa[b][1]);
            o.x += f0.x; o.y += f0.y; o.z += f1.x; o.w += f1.y;
            *(float4*)(dst + b * EMB + 4 * q) = o;
        }
    }
}

/* -------------------------------------------------- final softmax normalize */
__global__ void k_norm(float* __restrict__ out, const float* __restrict__ S) {
    size_t idx = (size_t)blockIdx.x * blockDim.x + threadIdx.x;
    if (idx < (size_t)B * OUT_BT) {
        int b = (int)(idx / OUT_BT);
        int t = (int)(idx / VOC) & (TLEN - 1);
        out[idx] = __fdividef(out[idx], __ldg(&S[t * B + b]));
    }
}

/* ------------------------------------------------------------------ driver */
extern "C" void kernel_launch(void* const* d_in, const int* in_sizes, int n_in,
                              void* d_out, int out_size) {
    (void)in_sizes; (void)n_in; (void)out_size;
    const float* x       = (const float*)d_in[0];
    const float* enc_w   = (const float*)d_in[1];
    const float* enc_b   = (const float*)d_in[2];
    const float* out_w   = (const float*)d_in[3];
    const float* out_b   = (const float*)d_in[4];
    const float* emb_out = (const float*)d_in[5];
    const float* emb_in  = (const float*)d_in[6];
    const float* ph0     = (const float*)d_in[7];
    const float* w_ih    = (const float*)d_in[8];
    const float* b_ih    = (const float*)d_in[9];
    const float* w_hh    = (const float*)d_in[10];
    const float* b_hh    = (const float*)d_in[11];
    const float* gumbel  = (const float*)d_in[12];
    float* out = (float*)d_out;

    float *p_enc0, *p_enc1, *p_img, *p_h0, *p_h1, *p_e, *p_Pp, *p_Sp, *p_S;
    cudaGetSymbolAddress((void**)&p_enc0, g_enc0);
    cudaGetSymbolAddress((void**)&p_enc1, g_enc1);
    cudaGetSymbolAddress((void**)&p_img,  g_img);
    cudaGetSymbolAddress((void**)&p_h0,   g_h0);
    cudaGetSymbolAddress((void**)&p_h1,   g_h1);
    cudaGetSymbolAddress((void**)&p_e,    g_e);
    cudaGetSymbolAddress((void**)&p_Pp,   g_Ppart);
    cudaGetSymbolAddress((void**)&p_Sp,   g_Spart);
    cudaGetSymbolAddress((void**)&p_S,    g_S);

    cudaFuncSetAttribute(k_main, cudaFuncAttributeMaxDynamicSharedMemorySize,
                         SMEM_MAIN);

    k_init<<<16, 256>>>(ph0, p_h0, p_e);

    k_gemv8<<<DIM / 8, 256>>>(x,      enc_w,             enc_b,       p_enc0, DIM, DIM, 1);
    k_gemv8<<<DIM / 8, 256>>>(p_enc0, enc_w + DIM * DIM, enc_b + DIM, p_enc1, DIM, DIM, 1);
    k_gemv8<<<EMB / 8, 256>>>(p_enc1, out_w,             out_b,       p_img,  DIM, EMB, 0);

    float* hbuf[2] = { p_h0, p_h1 };
    for (int t = 0; t < TLEN; t++) {
        if (t > 0)
            k_reduce<<<16, 256>>>(p_Pp, p_Sp, p_img, p_e, p_S + (t - 1) * B);
        k_gru2<<<HID / 8, 256>>>(p_e, hbuf[t & 1], w_ih, b_ih, w_hh, b_hh,
                                 hbuf[(t + 1) & 1]);
        k_main<<<NB_MAIN, 256, SMEM_MAIN>>>(hbuf[(t + 1) & 1], emb_out, emb_in,
                                            gumbel + (size_t)t * B * VOC,
                                            out + (size_t)t * VOC, p_Pp, p_Sp);
    }
    k_reduce<<<16, 256>>>(p_Pp, p_Sp, p_img, p_e, p_S + (TLEN - 1) * B);
    k_norm<<<(B * OUT_BT + 255) / 256, 256>>>(out, p_S);
}